// round 5
// baseline (speedup 1.0000x reference)
#include <cuda_runtime.h>
#include <stdint.h>

// out[b,t,n,f] = in[b,t,n,f] * ((n < set_size[b,t]) ? (ALPHA+BETA) : 0)
// B=32, T=64, N=128, F=256, fp32.
// ~half the rows masked to zero -> skip input loads there.
// 8 float4 per thread: all predicates first, batched predicated loads
// (MLP~8), then streaming stores (__stcs: output never re-read, keep L2
// for the read stream). Warp = 32 consecutive f4 = half an F-row, so the
// mask predicate is warp-uniform per iteration.

#define N_DIM 128
#define SCALE 1.1f
#define F4_PER_THREAD 8
#define THREADS 256

// total f4 = 32*64*128*(256/4) = 16,777,216

__global__ void __launch_bounds__(THREADS)
er_mask_scale_kernel(const float4* __restrict__ in,
                     const int* __restrict__ set_size,
                     float4* __restrict__ out)
{
    // block handles 2048 contiguous float4 (= 32 rows of 64 f4)
    unsigned base = blockIdx.x * (THREADS * F4_PER_THREAD) + threadIdx.x;

    bool live[F4_PER_THREAD];

    #pragma unroll
    for (int i = 0; i < F4_PER_THREAD; i++) {
        unsigned idx = base + i * THREADS;
        unsigned row = idx >> 6;              // (b,t,n)
        unsigned n   = row & (N_DIM - 1);
        unsigned bt  = row >> 7;
        int ss = __ldg(&set_size[bt]);        // L2-resident broadcast
        live[i] = ((int)n < ss);
    }

    float4 v[F4_PER_THREAD];
    #pragma unroll
    for (int i = 0; i < F4_PER_THREAD; i++) {
        v[i] = make_float4(0.f, 0.f, 0.f, 0.f);
        if (live[i]) v[i] = __ldg(&in[base + i * THREADS]);  // batched, MLP~8
    }

    #pragma unroll
    for (int i = 0; i < F4_PER_THREAD; i++) {
        if (live[i]) {
            v[i].x *= SCALE; v[i].y *= SCALE; v[i].z *= SCALE; v[i].w *= SCALE;
        }
        __stcs(&out[base + i * THREADS], v[i]);   // evict-first streaming store
    }
}

extern "C" void kernel_launch(void* const* d_in, const int* in_sizes, int n_in,
                              void* d_out, int out_size)
{
    const float4* in = (const float4*)d_in[0];
    const int* ss = (const int*)d_in[1];
    float4* out = (float4*)d_out;

    const unsigned total_f4 = 16777216u;
    const unsigned blocks = total_f4 / (THREADS * F4_PER_THREAD); // 8192

    er_mask_scale_kernel<<<blocks, THREADS>>>(in, ss, out);
}

// round 6
// speedup vs baseline: 1.0244x; 1.0244x over previous
#include <cuda_runtime.h>
#include <stdint.h>

// out[b,t,n,f] = in[b,t,n,f] * ((n < set_size[b,t]) ? (ALPHA+BETA) : 0)
// B=32, T=64, N=128, F=256, fp32.
// ~half the rows masked to zero -> skip input loads there.
// R4 shape (4 f4/thread, batched predicated loads) + streaming cache
// policy on both sides: __ldcs reads (read-once) and __stcs writes
// (never re-read) to keep L2 out of the way of the DRAM streams.
// Warp = 32 consecutive f4 = half an F-row -> warp-uniform predicate.

#define N_DIM 128
#define SCALE 1.1f
#define F4_PER_THREAD 4
#define THREADS 256

// total f4 = 32*64*128*(256/4) = 16,777,216

__global__ void __launch_bounds__(THREADS, 8)
er_mask_scale_kernel(const float4* __restrict__ in,
                     const int* __restrict__ set_size,
                     float4* __restrict__ out)
{
    // block handles 1024 contiguous float4 (= 16 rows of 64 f4)
    unsigned base = blockIdx.x * (THREADS * F4_PER_THREAD) + threadIdx.x;

    bool live[F4_PER_THREAD];

    #pragma unroll
    for (int i = 0; i < F4_PER_THREAD; i++) {
        unsigned idx = base + i * THREADS;
        unsigned row = idx >> 6;              // (b,t,n)
        unsigned n   = row & (N_DIM - 1);
        unsigned bt  = row >> 7;
        int ss = __ldg(&set_size[bt]);        // tiny, keep cached (reused heavily)
        live[i] = ((int)n < ss);
    }

    float4 v[F4_PER_THREAD];
    #pragma unroll
    for (int i = 0; i < F4_PER_THREAD; i++) {
        v[i] = make_float4(0.f, 0.f, 0.f, 0.f);
        if (live[i]) v[i] = __ldcs(&in[base + i * THREADS]);  // streaming read
    }

    #pragma unroll
    for (int i = 0; i < F4_PER_THREAD; i++) {
        if (live[i]) {
            v[i].x *= SCALE; v[i].y *= SCALE; v[i].z *= SCALE; v[i].w *= SCALE;
        }
        __stcs(&out[base + i * THREADS], v[i]);               // streaming write
    }
}

extern "C" void kernel_launch(void* const* d_in, const int* in_sizes, int n_in,
                              void* d_out, int out_size)
{
    const float4* in = (const float4*)d_in[0];
    const int* ss = (const int*)d_in[1];
    float4* out = (float4*)d_out;

    const unsigned total_f4 = 16777216u;
    const unsigned blocks = total_f4 / (THREADS * F4_PER_THREAD); // 16384

    er_mask_scale_kernel<<<blocks, THREADS>>>(in, ss, out);
}